// round 3
// baseline (speedup 1.0000x reference)
#include <cuda_runtime.h>

// ---------------- sizes ----------------
#define NB 16          // batch
#define CH 64          // width
#define SS 256         // spatial
#define M0 16
#define NMODE 32       // 16 top + 16 bottom kx modes
#define PLANE (SS*SS)  // 65536
#define SZH (NB*CH*PLANE)

typedef unsigned long long u64;

// ---------------- f32x2 helpers ----------------
__device__ __forceinline__ u64 fma2(u64 a, u64 b, u64 c) {
    u64 d;
    asm("fma.rn.f32x2 %0, %1, %2, %3;" : "=l"(d) : "l"(a), "l"(b), "l"(c));
    return d;
}
__device__ __forceinline__ u64 pack2(float lo, float hi) {
    u64 d;
    asm("mov.b64 %0, {%1, %2};" : "=l"(d)
        : "r"(__float_as_uint(lo)), "r"(__float_as_uint(hi)));
    return d;
}
__device__ __forceinline__ float2 unpk(u64 v) {
    unsigned lo, hi;
    asm("mov.b64 {%0, %1}, %2;" : "=r"(lo), "=r"(hi) : "l"(v));
    return make_float2(__uint_as_float(lo), __uint_as_float(hi));
}

// ---------------- device scratch ----------------
__device__ float  g_h[2][SZH];                 // ping-pong activations (b,c,x,y)
__device__ float2 g_A [NB*CH*SS*M0];           // after y-DFT: [b][c][x][ky]
__device__ float2 g_ft[NMODE*M0*NB*CH];        // [mode][b][i]
__device__ float2 g_oft[NMODE*M0*NB*CH];       // [mode][b][o]
__device__ float2 g_t [NB*CH*SS*M0];           // [b][o][x][ky]
__device__ float2 g_W [4*NMODE*M0*CH*CH];      // [blk][mode][i][o]
__device__ float2 g_trigY[M0*SS];              // (cos, -sin)(2 pi ky y/256)
__device__ float2 g_tx1[NMODE*SS];             // (c, s) of e^{-i 2pi kxp x/256}
__device__ float2 g_tx2[NMODE*SS];             // (-s, c)

// ---------------- trig tables (once per launch) ----------------
__global__ void k_trig() {
    int t = blockIdx.x * blockDim.x + threadIdx.x;
    if (t < M0 * SS) {
        int ky = t >> 8, y = t & 255;
        float s, c;
        sincospif((float)(ky * y) / 128.0f, &s, &c);   // exact integer arg
        g_trigY[t] = make_float2(c, -s);
    } else if (t < M0 * SS + NMODE * SS) {
        int k = t - M0 * SS;
        int m = k >> 8, x = k & 255;
        int kxp = (m < 16) ? m : (m - 32);
        float s, c;
        sincospif(-(float)(kxp * x) / 128.0f, &s, &c);
        g_tx1[k] = make_float2(c, s);
        g_tx2[k] = make_float2(-s, c);
    }
}

// ---------------- weight re-layout (once per launch) ----------------
__global__ void k_wprep(const float2* __restrict__ w1, const float2* __restrict__ w2) {
    int idx = blockIdx.x * blockDim.x + threadIdx.x;   // 4*512*4096
    int o   = idx & 63;
    int i   = (idx >> 6) & 63;
    int ky  = (idx >> 12) & 15;
    int m   = (idx >> 16) & 31;
    int blk = (idx >> 21);
    const float2* src = (m < 16) ? w1 : w2;
    int mx = (m < 16) ? m : (m - 16);
    g_W[idx] = src[((((long)blk * 64 + i) * 64 + o) * 16 + mx) * 16 + ky];
}

// ---------------- lift: x(b,x,y,3) @ fc0 -> g_h[0] (b,c,x,y) ----------------
__global__ void k_lift(const float* __restrict__ x, const float* __restrict__ w0,
                       const float* __restrict__ b0) {
    __shared__ float sw[192];
    __shared__ float sb[64];
    int t = threadIdx.x;
    if (t < 192) sw[t] = w0[t];
    if (t < 64)  sb[t] = b0[t];
    __syncthreads();
    int b = blockIdx.y, xx = blockIdx.x, y = t;
    const float* xp = x + (((long)b * SS + xx) * SS + y) * 3;
    float x0 = xp[0], x1 = xp[1], x2 = xp[2];
    float* out = g_h[0] + (long)b * CH * PLANE + xx * SS + y;
#pragma unroll
    for (int c = 0; c < CH; c++)
        out[(long)c * PLANE] = x0 * sw[c] + x1 * sw[64 + c] + x2 * sw[128 + c] + sb[c];
}

// ---------------- forward DFT over y: g_h[sel] -> g_A ----------------
// packed complex acc (re,im); v duplicated in smem; trig table staged (padded).
#define SMEM_DFTY (32*256*8 + 16*257*8)
__global__ void k_dfty(int sel) {
    extern __shared__ float smem[];
    float2* sh2 = (float2*)smem;          // 8192 f2: dup values
    float2* tr2 = sh2 + 32 * 256;         // 16 x 257 padded trig
    int b = blockIdx.z, c = blockIdx.y, x0 = blockIdx.x * 32;
    const float* src = g_h[sel] + (long)(b * CH + c) * PLANE + (long)x0 * SS;
    for (int k = threadIdx.x; k < 32 * 256; k += 256) {
        float v = src[k];
        sh2[k] = make_float2(v, v);
    }
    for (int k = threadIdx.x; k < 16 * 256; k += 256) {
        int ky = k >> 8, y = k & 255;
        tr2[ky * 257 + y] = g_trigY[k];
    }
    __syncthreads();
    int ky = threadIdx.x & 15;
    int rg = threadIdx.x >> 4;            // 16 groups x 2 rows
    const u64* v0p = (const u64*)(sh2 + (rg * 2) * 256);
    const u64* v1p = (const u64*)(sh2 + (rg * 2 + 1) * 256);
    const u64* tp  = (const u64*)(tr2 + ky * 257);
    u64 acc0 = 0ull, acc1 = 0ull;
#pragma unroll 8
    for (int y = 0; y < 256; y++) {
        u64 tw = tp[y];
        acc0 = fma2(v0p[y], tw, acc0);
        acc1 = fma2(v1p[y], tw, acc1);
    }
    const float sc = 1.0f / 65536.0f;
    float2 a0 = unpk(acc0), a1 = unpk(acc1);
    long base = ((long)(b * CH + c) * SS + (x0 + rg * 2)) * M0 + ky;
    g_A[base]      = make_float2(a0.x * sc, a0.y * sc);
    g_A[base + M0] = make_float2(a1.x * sc, a1.y * sc);
}

// ---------------- forward DFT over x: g_A -> g_ft ----------------
// A re/im duplicated in smem; twiddle tables via L1 (global)
#define SMEM_DFTX (2*4096*8)
__global__ void k_dftx() {
    extern __shared__ float smem[];
    float2* sax = (float2*)smem;   // dup a.x
    float2* say = sax + 4096;      // dup a.y
    int b = blockIdx.y, i = blockIdx.x;
    const float2* src = g_A + (long)(b * CH + i) * SS * M0;
    for (int k = threadIdx.x; k < SS * M0; k += 512) {
        float2 a = src[k];
        sax[k] = make_float2(a.x, a.x);
        say[k] = make_float2(a.y, a.y);
    }
    __syncthreads();
    int ky = threadIdx.x & 15;
    int m  = threadIdx.x >> 4;
    const u64* t1p = (const u64*)(g_tx1 + m * 256);
    const u64* t2p = (const u64*)(g_tx2 + m * 256);
    u64 acc = 0ull;
#pragma unroll 8
    for (int x = 0; x < 256; x++) {
        u64 ax = *(const u64*)&sax[x * M0 + ky];
        u64 ay = *(const u64*)&say[x * M0 + ky];
        acc = fma2(ax, t1p[x], acc);
        acc = fma2(ay, t2p[x], acc);
    }
    float2 r = unpk(acc);
    g_ft[(long)(m * M0 + ky) * (NB * CH) + b * CH + i] = r;
}

// ---------------- per-mode complex channel mix: g_ft -> g_oft ----------------
__global__ void k_mix(int blk) {
    __shared__ float2 F[NB * CH];     // [b][i]
    int mode = blockIdx.x;            // 0..511
    const float2* src = g_ft + (long)mode * (NB * CH);
    for (int k = threadIdx.x; k < NB * CH; k += 256) F[k] = src[k];
    __syncthreads();
    const float2* W = g_W + ((long)blk * (NMODE * M0) + mode) * (CH * CH);
    int o  = threadIdx.x & 63;
    int bg = threadIdx.x >> 6;        // 4 groups x 4 batches
    float accr[4] = {0.f, 0.f, 0.f, 0.f};
    float acci[4] = {0.f, 0.f, 0.f, 0.f};
    for (int i = 0; i < CH; i++) {
        float2 w = W[i * CH + o];
#pragma unroll
        for (int bb = 0; bb < 4; bb++) {
            float2 f = F[(bg * 4 + bb) * CH + i];
            accr[bb] += f.x * w.x - f.y * w.y;
            acci[bb] += f.x * w.y + f.y * w.x;
        }
    }
#pragma unroll
    for (int bb = 0; bb < 4; bb++)
        g_oft[(long)mode * (NB * CH) + (bg * 4 + bb) * CH + o] = make_float2(accr[bb], acci[bb]);
}

// ---------------- inverse DFT over x: g_oft -> g_t ----------------
__global__ void k_idftx() {
    __shared__ float2 so[NMODE * M0];
    int b = blockIdx.y, o = blockIdx.x;
    for (int k = threadIdx.x; k < NMODE * M0; k += 256)
        so[k] = g_oft[(long)k * (NB * CH) + b * CH + o];
    __syncthreads();
    int x = threadIdx.x;
    float accr[M0], acci[M0];
#pragma unroll
    for (int ky = 0; ky < M0; ky++) { accr[ky] = 0.f; acci[ky] = 0.f; }
    for (int m = 0; m < NMODE; m++) {
        int kxp = (m < 16) ? m : (m - 32);
        float s, c;
        sincospif((float)(kxp * x) / 128.0f, &s, &c);    // exact integer arg
#pragma unroll
        for (int ky = 0; ky < M0; ky++) {
            float2 a = so[m * M0 + ky];
            accr[ky] += a.x * c - a.y * s;
            acci[ky] += a.x * s + a.y * c;
        }
    }
    float2* dst = g_t + ((long)(b * CH + o) * SS + x) * M0;
#pragma unroll
    for (int ky = 0; ky < M0; ky++) dst[ky] = make_float2(accr[ky], acci[ky]);
}

// ---------------- block epilogue: inverse-y DFT + 1x1 conv + bias (+relu) ------
// 128 threads: 8 ogroups x 16 ythreads; 8 o x (4 y-pairs) register tile.
// sh_h natural floats (y-pairs via LDS.64); weights + t dup'd in smem.
#define SMEM_FINAL ((8192 + 8192 + 2048 + 2048 + 2048 + 2048 + 64) * 4)
__global__ void k_final(int sel, const float* __restrict__ cw, const float* __restrict__ cb,
                        int relu) {
    extern __shared__ float smem[];
    float*  sh_h = smem;                     // 8192 floats
    float2* cw2  = (float2*)(smem + 8192);   // 4096 f2: dup [i][o]
    float2* stx  = cw2 + 4096;               // 1024 f2: dup t.x [o][ky]
    float2* sty  = stx + 1024;               // 1024 f2: dup t.y
    float*  trc  = (float*)(sty + 1024);     // 2048: f*cos  [ky][yl]
    float*  trs  = trc + 2048;               // 2048: -f*sin
    float*  cbs  = trs + 2048;               // 64
    int t = threadIdx.x;                     // 128
    int b = blockIdx.z, xx = blockIdx.y, yb = blockIdx.x * 128;
    const float* hin = g_h[sel];

    for (int idx = t; idx < 8192; idx += 128) {
        int i = idx >> 7, yl = idx & 127;
        sh_h[idx] = hin[(long)(b * CH + i) * PLANE + xx * SS + yb + yl];
    }
    for (int idx = t; idx < 4096; idx += 128) {
        int o = idx >> 6, i = idx & 63;
        float w = cw[idx];
        cw2[i * 64 + o] = make_float2(w, w);
    }
    for (int idx = t; idx < 1024; idx += 128) {
        int o = idx >> 4, ky = idx & 15;
        float2 v = g_t[((long)(b * CH + o) * SS + xx) * M0 + ky];
        stx[idx] = make_float2(v.x, v.x);
        sty[idx] = make_float2(v.y, v.y);
    }
    for (int idx = t; idx < 2048; idx += 128) {
        int ky = idx >> 7, yl = idx & 127;
        float2 e = g_trigY[ky * 256 + yb + yl];   // (c, -s)
        float f = ky ? 2.f : 1.f;
        trc[idx] = f * e.x;
        trs[idx] = f * e.y;
    }
    if (t < 64) cbs[t] = cb[t];
    __syncthreads();

    int og = t >> 4;       // 8 groups of 8 output channels
    int yth = t & 15;      // y pairs at 2*yth + 32*p
    u64 acc[8][4];
#pragma unroll
    for (int oo = 0; oo < 8; oo++)
#pragma unroll
        for (int p = 0; p < 4; p++) acc[oo][p] = 0ull;

    // 1x1 conv path
    for (int i = 0; i < CH; i++) {
        u64 h2[4];
#pragma unroll
        for (int p = 0; p < 4; p++)
            h2[p] = *(const u64*)&sh_h[i * 128 + 2 * yth + 32 * p];
#pragma unroll
        for (int oo = 0; oo < 8; oo++) {
            u64 w2 = *(const u64*)&cw2[i * 64 + og * 8 + oo];
#pragma unroll
            for (int p = 0; p < 4; p++) acc[oo][p] = fma2(w2, h2[p], acc[oo][p]);
        }
    }
    // spectral inverse-y path
    for (int ky = 0; ky < M0; ky++) {
        u64 gc[4], gs[4];
#pragma unroll
        for (int p = 0; p < 4; p++) {
            gc[p] = *(const u64*)&trc[ky * 128 + 2 * yth + 32 * p];
            gs[p] = *(const u64*)&trs[ky * 128 + 2 * yth + 32 * p];
        }
#pragma unroll
        for (int oo = 0; oo < 8; oo++) {
            u64 tx = *(const u64*)&stx[(og * 8 + oo) * 16 + ky];
            u64 ty = *(const u64*)&sty[(og * 8 + oo) * 16 + ky];
#pragma unroll
            for (int p = 0; p < 4; p++) {
                acc[oo][p] = fma2(tx, gc[p], acc[oo][p]);
                acc[oo][p] = fma2(ty, gs[p], acc[oo][p]);
            }
        }
    }
    float* hout = g_h[sel ^ 1];
#pragma unroll
    for (int oo = 0; oo < 8; oo++) {
        int o = og * 8 + oo;
        float bias = cbs[o];
#pragma unroll
        for (int p = 0; p < 4; p++) {
            float2 v = unpk(acc[oo][p]);
            v.x += bias; v.y += bias;
            if (relu) { v.x = fmaxf(v.x, 0.f); v.y = fmaxf(v.y, 0.f); }
            *(float2*)&hout[(long)(b * CH + o) * PLANE + xx * SS + yb + 2 * yth + 32 * p] = v;
        }
    }
}

// ---------------- fused fc1 + relu + fc2 ----------------
// 256 threads: 32 jgroups x 8 ythreads; 4 j-pairs x 8 y register tile.
// w1 natural (j-pairs via LDS.64); h duplicated in smem.
#define SMEM_FC ((8192 + 16384 + 256 + 256 + 64) * 4)
__global__ void k_fc(int sel, const float* __restrict__ fc1w, const float* __restrict__ fc1b,
                     const float* __restrict__ fc2w, const float* __restrict__ fc2b,
                     float* __restrict__ out) {
    extern __shared__ float smem[];
    float2* sh2 = (float2*)smem;     // 4096 f2: dup h [i][y]
    float*  w1s = smem + 8192;       // 16384
    float*  b1s = w1s + 16384;       // 256
    float*  f2s = b1s + 256;         // 256
    float*  sred = f2s + 256;        // 64
    int t = threadIdx.x;             // 256
    int b = blockIdx.z, xx = blockIdx.y, yb = blockIdx.x * 64;
    const float* hin = g_h[sel];

    for (int idx = t; idx < 4096; idx += 256) {
        int i = idx >> 6, yl = idx & 63;
        float v = hin[(long)(b * CH + i) * PLANE + xx * SS + yb + yl];
        sh2[idx] = make_float2(v, v);
    }
    for (int idx = t; idx < 16384; idx += 256) w1s[idx] = fc1w[idx];
    if (t < 256) { b1s[t] = fc1b[t]; f2s[t] = fc2w[t]; }
    if (t < 64)  sred[t] = fc2b[0];
    __syncthreads();

    int jg = t >> 3;   // 32 groups x 8 j
    int yth = t & 7;   // y = yth + 8*yy
    u64 acc[4][8];
#pragma unroll
    for (int jp = 0; jp < 4; jp++) {
        u64 binit = pack2(b1s[jg * 8 + 2 * jp], b1s[jg * 8 + 2 * jp + 1]);
#pragma unroll
        for (int yy = 0; yy < 8; yy++) acc[jp][yy] = binit;
    }

    for (int c = 0; c < CH; c++) {
        u64 h2[8];
#pragma unroll
        for (int yy = 0; yy < 8; yy++)
            h2[yy] = *(const u64*)&sh2[c * 64 + yth + 8 * yy];
#pragma unroll
        for (int jp = 0; jp < 4; jp++) {
            u64 w2 = *(const u64*)&w1s[c * 256 + jg * 8 + 2 * jp];
#pragma unroll
            for (int yy = 0; yy < 8; yy++) acc[jp][yy] = fma2(w2, h2[yy], acc[jp][yy]);
        }
    }
    float p[8];
#pragma unroll
    for (int yy = 0; yy < 8; yy++) p[yy] = 0.f;
#pragma unroll
    for (int jp = 0; jp < 4; jp++) {
        float fa = f2s[jg * 8 + 2 * jp], fb = f2s[jg * 8 + 2 * jp + 1];
#pragma unroll
        for (int yy = 0; yy < 8; yy++) {
            float2 v = unpk(acc[jp][yy]);
            p[yy] += fmaxf(v.x, 0.f) * fa + fmaxf(v.y, 0.f) * fb;
        }
    }
#pragma unroll
    for (int yy = 0; yy < 8; yy++) atomicAdd(&sred[yth + 8 * yy], p[yy]);
    __syncthreads();
    if (t < 64) out[((long)b * SS + xx) * SS + yb + t] = sred[t];
}

// ---------------- launch ----------------
extern "C" void kernel_launch(void* const* d_in, const int* in_sizes, int n_in,
                              void* d_out, int out_size) {
    const float* x     = (const float*)d_in[0];
    const float* fc0w  = (const float*)d_in[1];
    const float* fc0b  = (const float*)d_in[2];
    const float2* w1   = (const float2*)d_in[3];
    const float2* w2   = (const float2*)d_in[4];
    const float* cw    = (const float*)d_in[5];
    const float* cb    = (const float*)d_in[6];
    const float* fc1w  = (const float*)d_in[7];
    const float* fc1b  = (const float*)d_in[8];
    const float* fc2w  = (const float*)d_in[9];
    const float* fc2b  = (const float*)d_in[10];
    float* out = (float*)d_out;

    cudaFuncSetAttribute(k_dfty,  cudaFuncAttributeMaxDynamicSharedMemorySize, SMEM_DFTY);
    cudaFuncSetAttribute(k_dftx,  cudaFuncAttributeMaxDynamicSharedMemorySize, SMEM_DFTX);
    cudaFuncSetAttribute(k_final, cudaFuncAttributeMaxDynamicSharedMemorySize, SMEM_FINAL);
    cudaFuncSetAttribute(k_fc,    cudaFuncAttributeMaxDynamicSharedMemorySize, SMEM_FC);

    k_trig<<<48, 256>>>();
    k_wprep<<<(4 * NMODE * M0 * CH * CH) / 256, 256>>>(w1, w2);
    k_lift<<<dim3(SS, NB), 256>>>(x, fc0w, fc0b);

    int cur = 0;
    for (int blk = 0; blk < 4; blk++) {
        k_dfty<<<dim3(8, CH, NB), 256, SMEM_DFTY>>>(cur);
        k_dftx<<<dim3(CH, NB), 512, SMEM_DFTX>>>();
        k_mix<<<NMODE * M0, 256>>>(blk);
        k_idftx<<<dim3(CH, NB), 256>>>();
        k_final<<<dim3(2, SS, NB), 128, SMEM_FINAL>>>(cur, cw + (long)blk * CH * CH,
                                                      cb + blk * CH, blk < 3 ? 1 : 0);
        cur ^= 1;
    }
    k_fc<<<dim3(4, SS, NB), 256, SMEM_FC>>>(cur, fc1w, fc1b, fc2w, fc2b, out);
}

// round 5
// speedup vs baseline: 1.1055x; 1.1055x over previous
#include <cuda_runtime.h>

// ---------------- sizes ----------------
#define NB 16
#define CH 64
#define SS 256
#define M0 16
#define NMODE 32
#define PLANE (SS*SS)
#define SZH (NB*CH*PLANE)

typedef unsigned long long u64;

// ---------------- f32x2 helpers ----------------
__device__ __forceinline__ u64 fma2(u64 a, u64 b, u64 c) {
    u64 d;
    asm("fma.rn.f32x2 %0, %1, %2, %3;" : "=l"(d) : "l"(a), "l"(b), "l"(c));
    return d;
}
__device__ __forceinline__ float2 unpk(u64 v) {
    unsigned lo, hi;
    asm("mov.b64 {%0, %1}, %2;" : "=r"(lo), "=r"(hi) : "l"(v));
    return make_float2(__uint_as_float(lo), __uint_as_float(hi));
}

// ---------------- device scratch ----------------
__device__ float  g_h[2][SZH];                 // ping-pong activations (b,c,x,y)
__device__ float  g_Ar[NB*CH*M0*SS];           // y-DFT real: [b][c][ky][x]
__device__ float  g_Ai[NB*CH*M0*SS];           // y-DFT imag
__device__ float2 g_ft[NMODE*M0*NB*CH];        // [mode][b][i]
__device__ float2 g_oft[NMODE*M0*NB*CH];       // [mode][b][o]
__device__ float2 g_t [NB*CH*SS*M0];           // [b][o][x][ky]
__device__ float2 g_W [4*NMODE*M0*CH*CH];      // [blk][mode][i][o]
__device__ float  g_tyc[M0*SS];                // cos(2 pi ky y/256)
__device__ float  g_tys[M0*SS];                // -sin(2 pi ky y/256)
__device__ float  g_xc[NMODE*SS];              // cos(2 pi kxp x/256)
__device__ float  g_xs[NMODE*SS];              // sin(2 pi kxp x/256)

// ---------------- trig tables (once per launch) ----------------
__global__ void k_trig() {
    int t = blockIdx.x * blockDim.x + threadIdx.x;
    if (t < M0 * SS) {
        int ky = t >> 8, y = t & 255;
        float s, c;
        sincospif((float)(ky * y) / 128.0f, &s, &c);   // exact integer arg
        g_tyc[t] = c;
        g_tys[t] = -s;
    } else if (t < M0 * SS + NMODE * SS) {
        int k = t - M0 * SS;
        int m = k >> 8, x = k & 255;
        int kxp = (m < 16) ? m : (m - 32);
        float s, c;
        sincospif((float)(kxp * x) / 128.0f, &s, &c);
        g_xc[k] = c;
        g_xs[k] = s;
    }
}

// ---------------- weight re-layout (once per launch) ----------------
__global__ void k_wprep(const float2* __restrict__ w1, const float2* __restrict__ w2) {
    int idx = blockIdx.x * blockDim.x + threadIdx.x;
    int o   = idx & 63;
    int i   = (idx >> 6) & 63;
    int ky  = (idx >> 12) & 15;
    int m   = (idx >> 16) & 31;
    int blk = (idx >> 21);
    const float2* src = (m < 16) ? w1 : w2;
    int mx = (m < 16) ? m : (m - 16);
    g_W[idx] = src[((((long)blk * 64 + i) * 64 + o) * 16 + mx) * 16 + ky];
}

// ---------------- lift ----------------
__global__ void k_lift(const float* __restrict__ x, const float* __restrict__ w0,
                       const float* __restrict__ b0) {
    __shared__ float sw[192];
    __shared__ float sb[64];
    int t = threadIdx.x;
    if (t < 192) sw[t] = w0[t];
    if (t < 64)  sb[t] = b0[t];
    __syncthreads();
    int b = blockIdx.y, xx = blockIdx.x, y = t;
    const float* xp = x + (((long)b * SS + xx) * SS + y) * 3;
    float x0 = xp[0], x1 = xp[1], x2 = xp[2];
    float* out = g_h[0] + (long)b * CH * PLANE + xx * SS + y;
#pragma unroll
    for (int c = 0; c < CH; c++)
        out[(long)c * PLANE] = x0 * sw[c] + x1 * sw[64 + c] + x2 * sw[128 + c] + sb[c];
}

// ---------------- forward DFT over y ----------------
// y-pair packing: accR2 += (v,v')·(c,c'), accI2 += (v,v')·(-s,-s'); end: horizontal add.
// 256 thr = 16 ky x 16 rowgroups x 4 rows; smem rows padded to 258.
#define SMEM_DFTY ((64*258 + 2*16*258)*4)
__global__ void __launch_bounds__(256) k_dfty(int sel) {
    extern __shared__ float sm[];
    float* sh = sm;               // [64][258]
    float* tc = sh + 64 * 258;    // [16][258]
    float* ts = tc + 16 * 258;
    int b = blockIdx.z, c = blockIdx.y, x0 = blockIdx.x * 64;
    const float* src = g_h[sel] + (long)(b * CH + c) * PLANE + (long)x0 * SS;
    for (int k = threadIdx.x; k < 64 * 256; k += 256) {
        int r = k >> 8, y = k & 255;
        sh[r * 258 + y] = src[k];
    }
    for (int k = threadIdx.x; k < 16 * 256; k += 256) {
        int ky = k >> 8, y = k & 255;
        tc[ky * 258 + y] = g_tyc[k];
        ts[ky * 258 + y] = g_tys[k];
    }
    __syncthreads();
    int ky = threadIdx.x & 15, rg = threadIdx.x >> 4;
    const u64* cp = (const u64*)(tc + ky * 258);
    const u64* sp = (const u64*)(ts + ky * 258);
    const u64* v0 = (const u64*)(sh + (rg * 4 + 0) * 258);
    const u64* v1 = (const u64*)(sh + (rg * 4 + 1) * 258);
    const u64* v2 = (const u64*)(sh + (rg * 4 + 2) * 258);
    const u64* v3 = (const u64*)(sh + (rg * 4 + 3) * 258);
    u64 aR0 = 0, aR1 = 0, aR2 = 0, aR3 = 0;
    u64 aI0 = 0, aI1 = 0, aI2 = 0, aI3 = 0;
#pragma unroll 4
    for (int yp = 0; yp < 128; yp++) {
        u64 c2 = cp[yp], s2 = sp[yp];
        u64 w0 = v0[yp]; aR0 = fma2(w0, c2, aR0); aI0 = fma2(w0, s2, aI0);
        u64 w1 = v1[yp]; aR1 = fma2(w1, c2, aR1); aI1 = fma2(w1, s2, aI1);
        u64 w2 = v2[yp]; aR2 = fma2(w2, c2, aR2); aI2 = fma2(w2, s2, aI2);
        u64 w3 = v3[yp]; aR3 = fma2(w3, c2, aR3); aI3 = fma2(w3, s2, aI3);
    }
    const float sc = 1.0f / 65536.0f;
    long base = ((long)((b * CH + c) * M0 + ky)) * SS + x0 + rg * 4;
    float2 r, i;
    r = unpk(aR0); i = unpk(aI0); g_Ar[base + 0] = (r.x + r.y) * sc; g_Ai[base + 0] = (i.x + i.y) * sc;
    r = unpk(aR1); i = unpk(aI1); g_Ar[base + 1] = (r.x + r.y) * sc; g_Ai[base + 1] = (i.x + i.y) * sc;
    r = unpk(aR2); i = unpk(aI2); g_Ar[base + 2] = (r.x + r.y) * sc; g_Ai[base + 2] = (i.x + i.y) * sc;
    r = unpk(aR3); i = unpk(aI3); g_Ar[base + 3] = (r.x + r.y) * sc; g_Ai[base + 3] = (i.x + i.y) * sc;
}

// ---------------- forward DFT over x ----------------
// x-pair packing; ft = sum_x (Ar+iAi)(c - i s): re = Ar c + Ai s ; im = Ai c - Ar s
__global__ void __launch_bounds__(512) k_dftx() {
    __shared__ float sAr[16 * 258];
    __shared__ float sAi[16 * 258];
    int b = blockIdx.y, i = blockIdx.x;
    long abase = (long)((b * CH + i) * M0) * SS;
    for (int k = threadIdx.x; k < 4096; k += 512) {
        int ky = k >> 8, x = k & 255;
        sAr[ky * 258 + x] = g_Ar[abase + k];
        sAi[ky * 258 + x] = g_Ai[abase + k];
    }
    __syncthreads();
    int ky = threadIdx.x & 15, m = threadIdx.x >> 4;
    const u64* arp = (const u64*)(sAr + ky * 258);
    const u64* aip = (const u64*)(sAi + ky * 258);
    const u64* cp = (const u64*)(g_xc + m * 256);
    const u64* sp = (const u64*)(g_xs + m * 256);
    u64 RC = 0, IS = 0, IC = 0, RS = 0;
#pragma unroll 4
    for (int xp = 0; xp < 128; xp++) {
        u64 c2 = cp[xp], s2 = sp[xp];
        u64 ar = arp[xp], ai = aip[xp];
        RC = fma2(ar, c2, RC);
        IS = fma2(ai, s2, IS);
        IC = fma2(ai, c2, IC);
        RS = fma2(ar, s2, RS);
    }
    float2 rc = unpk(RC), is = unpk(IS), ic = unpk(IC), rs = unpk(RS);
    float re = rc.x + rc.y + is.x + is.y;
    float im = ic.x + ic.y - rs.x - rs.y;
    g_ft[(long)(m * M0 + ky) * (NB * CH) + b * CH + i] = make_float2(re, im);
}

// ---------------- per-mode complex channel mix ----------------
__global__ void k_mix(int blk) {
    __shared__ float2 F[NB * CH];
    int mode = blockIdx.x;
    const float2* src = g_ft + (long)mode * (NB * CH);
    for (int k = threadIdx.x; k < NB * CH; k += 256) F[k] = src[k];
    __syncthreads();
    const float2* W = g_W + ((long)blk * (NMODE * M0) + mode) * (CH * CH);
    int o  = threadIdx.x & 63;
    int bg = threadIdx.x >> 6;
    float accr[4] = {0.f, 0.f, 0.f, 0.f};
    float acci[4] = {0.f, 0.f, 0.f, 0.f};
    for (int i = 0; i < CH; i++) {
        float2 w = W[i * CH + o];
#pragma unroll
        for (int bb = 0; bb < 4; bb++) {
            float2 f = F[(bg * 4 + bb) * CH + i];
            accr[bb] += f.x * w.x - f.y * w.y;
            acci[bb] += f.x * w.y + f.y * w.x;
        }
    }
#pragma unroll
    for (int bb = 0; bb < 4; bb++)
        g_oft[(long)mode * (NB * CH) + (bg * 4 + bb) * CH + o] = make_float2(accr[bb], acci[bb]);
}

// ---------------- inverse DFT over x ----------------
__global__ void k_idftx() {
    __shared__ float2 so[NMODE * M0];
    int b = blockIdx.y, o = blockIdx.x;
    for (int k = threadIdx.x; k < NMODE * M0; k += 256)
        so[k] = g_oft[(long)k * (NB * CH) + b * CH + o];
    __syncthreads();
    int x = threadIdx.x;
    float accr[M0], acci[M0];
#pragma unroll
    for (int ky = 0; ky < M0; ky++) { accr[ky] = 0.f; acci[ky] = 0.f; }
    for (int m = 0; m < NMODE; m++) {
        int kxp = (m < 16) ? m : (m - 32);
        float s, c;
        sincospif((float)(kxp * x) / 128.0f, &s, &c);
#pragma unroll
        for (int ky = 0; ky < M0; ky++) {
            float2 a = so[m * M0 + ky];
            accr[ky] += a.x * c - a.y * s;
            acci[ky] += a.x * s + a.y * c;
        }
    }
    float2* dst = g_t + ((long)(b * CH + o) * SS + x) * M0;
#pragma unroll
    for (int ky = 0; ky < M0; ky++) dst[ky] = make_float2(accr[ky], acci[ky]);
}

// ---------------- block epilogue as one K=96 GEMM ----------------
// rows 0..63: conv (A=cw dup, B=h);  64..79: 2*t.x vs cos;  80..95: 2*t.y vs -sin
// 128 thr = 4 warps x 16-o blocks; lane = y-pair; y-tile 128 (2 pair slots).
#define SMEM_FINAL ((96*130 + 96*128 + 64)*4)
__global__ void __launch_bounds__(128) k_final(int sel, const float* __restrict__ cw,
                                               const float* __restrict__ cb, int relu) {
    extern __shared__ float sm[];
    float* Bm  = sm;                 // [96][130]
    float* Ad  = Bm + 96 * 130;      // [96][128] dup pairs
    float* cbs = Ad + 96 * 128;
    int t = threadIdx.x;
    int b = blockIdx.z, xx = blockIdx.y, yb = blockIdx.x * 128;
    const float* hin = g_h[sel];

    for (int idx = t; idx < 64 * 128; idx += 128) {
        int i = idx >> 7, yl = idx & 127;
        Bm[i * 130 + yl] = hin[(long)(b * CH + i) * PLANE + xx * SS + yb + yl];
    }
    for (int idx = t; idx < 16 * 128; idx += 128) {
        int ky = idx >> 7, yl = idx & 127;
        Bm[(64 + ky) * 130 + yl] = g_tyc[ky * 256 + yb + yl];
        Bm[(80 + ky) * 130 + yl] = g_tys[ky * 256 + yb + yl];
    }
    for (int idx = t; idx < 4096; idx += 128) {
        int o = idx >> 6, i = idx & 63;
        float w = cw[idx];
        Ad[i * 128 + 2 * o] = w;
        Ad[i * 128 + 2 * o + 1] = w;
    }
    for (int idx = t; idx < 1024; idx += 128) {
        int o = idx >> 4, ky = idx & 15;
        float2 v = g_t[((long)(b * CH + o) * SS + xx) * M0 + ky];
        float f = ky ? 2.f : 1.f;
        Ad[(64 + ky) * 128 + 2 * o] = f * v.x;
        Ad[(64 + ky) * 128 + 2 * o + 1] = f * v.x;
        Ad[(80 + ky) * 128 + 2 * o] = f * v.y;
        Ad[(80 + ky) * 128 + 2 * o + 1] = f * v.y;
    }
    if (t < 64) cbs[t] = cb[t];
    __syncthreads();

    int wid = t >> 5, lane = t & 31;
    int ob = wid * 16;
    u64 acc0[16], acc1[16];
#pragma unroll
    for (int oo = 0; oo < 16; oo++) { acc0[oo] = 0; acc1[oo] = 0; }

#pragma unroll 2
    for (int k = 0; k < 96; k++) {
        u64 b0 = *(const u64*)&Bm[k * 130 + 2 * lane];
        u64 b1 = *(const u64*)&Bm[k * 130 + 64 + 2 * lane];
        const u64* ap = (const u64*)&Ad[k * 128 + 2 * ob];
#pragma unroll
        for (int oo = 0; oo < 16; oo++) {
            u64 a = ap[oo];
            acc0[oo] = fma2(a, b0, acc0[oo]);
            acc1[oo] = fma2(a, b1, acc1[oo]);
        }
    }
    float* hout = g_h[sel ^ 1];
#pragma unroll
    for (int oo = 0; oo < 16; oo++) {
        float bias = cbs[ob + oo];
        long obase = (long)(b * CH + ob + oo) * PLANE + xx * SS + yb + 2 * lane;
        float2 v0 = unpk(acc0[oo]);
        v0.x += bias; v0.y += bias;
        if (relu) { v0.x = fmaxf(v0.x, 0.f); v0.y = fmaxf(v0.y, 0.f); }
        *(float2*)&hout[obase] = v0;
        float2 v1 = unpk(acc1[oo]);
        v1.x += bias; v1.y += bias;
        if (relu) { v1.x = fmaxf(v1.x, 0.f); v1.y = fmaxf(v1.y, 0.f); }
        *(float2*)&hout[obase + 64] = v1;
    }
}

// ---------------- fused fc1 + relu + fc2 ----------------
// j-pair packed acc (w1 pairs natural, broadcast); h dup'd (33KB).
// 256 thr = 8 warps x 32-j blocks; lane = y; y-tile 64 (2 slots: lane, lane+32).
#define SMEM_FC ((64*130 + 16384 + 256 + 256 + 64)*4)
__global__ void __launch_bounds__(256) k_fc(int sel, const float* __restrict__ fc1w,
                                            const float* __restrict__ fc1b,
                                            const float* __restrict__ fc2w,
                                            const float* __restrict__ fc2b,
                                            float* __restrict__ out) {
    extern __shared__ float sm[];
    float* hd   = sm;                // [64][130] dup pairs
    float* w1s  = hd + 64 * 130;     // [64][256]
    float* b1s  = w1s + 16384;
    float* f2s  = b1s + 256;
    float* sred = f2s + 256;
    int t = threadIdx.x;
    int b = blockIdx.z, xx = blockIdx.y, yb = blockIdx.x * 64;
    const float* hin = g_h[sel];

    for (int idx = t; idx < 4096; idx += 256) {
        int c = idx >> 6, yl = idx & 63;
        float v = hin[(long)(b * CH + c) * PLANE + xx * SS + yb + yl];
        hd[c * 130 + 2 * yl] = v;
        hd[c * 130 + 2 * yl + 1] = v;
    }
    for (int idx = t; idx < 16384; idx += 256) w1s[idx] = fc1w[idx];
    if (t < 256) { b1s[t] = fc1b[t]; f2s[t] = fc2w[t]; }
    if (t < 64)  sred[t] = fc2b[0];
    __syncthreads();

    int wid = t >> 5, lane = t & 31;
    int jb = wid * 32;
    u64 acc0[16], acc1[16];
#pragma unroll
    for (int jp = 0; jp < 16; jp++) {
        u64 bi = *(const u64*)&b1s[jb + 2 * jp];
        acc0[jp] = bi;
        acc1[jp] = bi;
    }
#pragma unroll 2
    for (int c = 0; c < CH; c++) {
        u64 h0 = *(const u64*)&hd[c * 130 + 2 * lane];
        u64 h1 = *(const u64*)&hd[c * 130 + 64 + 2 * lane];
        const u64* wp = (const u64*)&w1s[c * 256 + jb];
#pragma unroll
        for (int jp = 0; jp < 16; jp++) {
            u64 w = wp[jp];
            acc0[jp] = fma2(w, h0, acc0[jp]);
            acc1[jp] = fma2(w, h1, acc1[jp]);
        }
    }
    float p0 = 0.f, p1 = 0.f;
#pragma unroll
    for (int jp = 0; jp < 16; jp++) {
        float fa = f2s[jb + 2 * jp], fb = f2s[jb + 2 * jp + 1];
        float2 v0 = unpk(acc0[jp]);
        p0 += fmaxf(v0.x, 0.f) * fa + fmaxf(v0.y, 0.f) * fb;
        float2 v1 = unpk(acc1[jp]);
        p1 += fmaxf(v1.x, 0.f) * fa + fmaxf(v1.y, 0.f) * fb;
    }
    atomicAdd(&sred[lane], p0);
    atomicAdd(&sred[32 + lane], p1);
    __syncthreads();
    if (t < 64) out[((long)b * SS + xx) * SS + yb + t] = sred[t];
}

// ---------------- launch ----------------
extern "C" void kernel_launch(void* const* d_in, const int* in_sizes, int n_in,
                              void* d_out, int out_size) {
    const float* x     = (const float*)d_in[0];
    const float* fc0w  = (const float*)d_in[1];
    const float* fc0b  = (const float*)d_in[2];
    const float2* w1   = (const float2*)d_in[3];
    const float2* w2   = (const float2*)d_in[4];
    const float* cw    = (const float*)d_in[5];
    const float* cb    = (const float*)d_in[6];
    const float* fc1w  = (const float*)d_in[7];
    const float* fc1b  = (const float*)d_in[8];
    const float* fc2w  = (const float*)d_in[9];
    const float* fc2b  = (const float*)d_in[10];
    float* out = (float*)d_out;

    cudaFuncSetAttribute(k_dfty,  cudaFuncAttributeMaxDynamicSharedMemorySize, SMEM_DFTY);
    cudaFuncSetAttribute(k_final, cudaFuncAttributeMaxDynamicSharedMemorySize, SMEM_FINAL);
    cudaFuncSetAttribute(k_fc,    cudaFuncAttributeMaxDynamicSharedMemorySize, SMEM_FC);

    k_trig<<<48, 256>>>();
    k_wprep<<<(4 * NMODE * M0 * CH * CH) / 256, 256>>>(w1, w2);
    k_lift<<<dim3(SS, NB), 256>>>(x, fc0w, fc0b);

    int cur = 0;
    for (int blk = 0; blk < 4; blk++) {
        k_dfty<<<dim3(4, CH, NB), 256, SMEM_DFTY>>>(cur);
        k_dftx<<<dim3(CH, NB), 512>>>();
        k_mix<<<NMODE * M0, 256>>>(blk);
        k_idftx<<<dim3(CH, NB), 256>>>();
        k_final<<<dim3(2, SS, NB), 128, SMEM_FINAL>>>(cur, cw + (long)blk * CH * CH,
                                                      cb + blk * CH, blk < 3 ? 1 : 0);
        cur ^= 1;
    }
    k_fc<<<dim3(4, SS, NB), 256, SMEM_FC>>>(cur, fc1w, fc1b, fc2w, fc2b, out);
}